// round 3
// baseline (speedup 1.0000x reference)
#include <cuda_runtime.h>

#define NN 100000
#define NE 1600000
#define NB_SCAN ((NN + 255) / 256)   // 391

// ---------------- scratch (static __device__ — no allocations) ----------------
__device__ int   g_deg[NN];
__device__ int   g_cur[NN];
__device__ float g_dinv[NN];
__device__ int   g_offs[NN + 1];
__device__ int   g_csrc[NE];
__device__ int   g_bsum[NB_SCAN];
__device__ int   g_flag;                 // !=0 -> edge_index stored as int32
__device__ float g_y [NN * 64];
__device__ float g_h [NN * 64];
__device__ float g_y3[NN * 16];

__device__ __forceinline__ float* bufsel(int s, float* ext) {
    if (s == 0) return g_y;
    if (s == 1) return g_h;
    if (s == 2) return g_y3;
    return ext;
}

// ---------------- dtype detect ----------------
// int64 indices < 100000 have zero high words; int32 data has nonzero odd words.
__global__ void k_detect(const int* __restrict__ w) {
    __shared__ int sf;
    int t = threadIdx.x;
    if (t == 0) sf = 0;
    __syncthreads();
    int f = 0;
    for (int i = t; i < 2048; i += 256)
        if (w[2 * i + 1] != 0) f = 1;
    if (f) atomicOr(&sf, 1);
    __syncthreads();
    if (t == 0) g_flag = sf;
}

__device__ __forceinline__ int edge_val(const int* __restrict__ w, int elem, bool i32) {
    return i32 ? w[elem] : ((const int2*)w)[elem].x;
}

// ---------------- CSR build ----------------
__global__ void k_hist(const int* __restrict__ w) {
    bool i32 = (g_flag != 0);
    int e = blockIdx.x * 256 + threadIdx.x;   // grid covers NE exactly
    int d = edge_val(w, NE + e, i32);
    atomicAdd(&g_deg[d], 1);
}

// block-local exclusive scan of deg; also emits dinv + block sums
__global__ void k_scan1() {
    __shared__ int s[256];
    int t = threadIdx.x;
    int i = blockIdx.x * 256 + t;
    int v = (i < NN) ? g_deg[i] : 0;
    if (i < NN) g_dinv[i] = rsqrtf((float)(v + 1));   // +1 self loop
    s[t] = v;
    __syncthreads();
    for (int o = 1; o < 256; o <<= 1) {
        int u = (t >= o) ? s[t - o] : 0;
        __syncthreads();
        s[t] += u;
        __syncthreads();
    }
    if (i < NN) g_offs[i] = s[t] - v;           // exclusive within block
    if (t == 255) g_bsum[blockIdx.x] = s[255];  // block total
}

// each block reduces its own prefix over the 391 block sums, applies it,
// and initializes write cursors
__global__ void k_scan23() {
    __shared__ int sm[256];
    int bid = blockIdx.x, t = threadIdx.x;
    int partial = 0;
    for (int j = t; j < bid; j += 256) partial += g_bsum[j];
    sm[t] = partial;
    __syncthreads();
    for (int o = 128; o > 0; o >>= 1) {
        if (t < o) sm[t] += sm[t + o];
        __syncthreads();
    }
    int boff = sm[0];
    int i = bid * 256 + t;
    if (i < NN) {
        int o = g_offs[i] + boff;
        g_offs[i] = o;
        g_cur[i]  = o;
    }
    if (i == 0) g_offs[NN] = NE;
}

__global__ void k_scatter(const int* __restrict__ w) {
    bool i32 = (g_flag != 0);
    int e = blockIdx.x * 256 + threadIdx.x;   // grid covers NE exactly
    int s = edge_val(w, e, i32);
    int d = edge_val(w, NE + e, i32);
    int pos = atomicAdd(&g_cur[d], 1);
    g_csrc[pos] = s;
}

// ---------------- linear: Y = dinv ⊙ (X @ W), register-blocked ----------------
template <int IN, int OUT, int R>
__global__ void k_linear(const float* __restrict__ X, const float* __restrict__ W,
                         int ysel) {
    constexpr int CG   = OUT / 4;        // float4 groups per row
    constexpr int ROWS = (256 / CG) * R; // rows per block
    float* Y = bufsel(ysel, nullptr);

    extern __shared__ float smem[];
    float*  Xs = smem;                          // ROWS * IN floats
    float4* Ws = (float4*)(smem + ROWS * IN);   // IN * CG float4s

    int t = threadIdx.x;
    for (int i = t; i < IN * CG; i += 256)
        Ws[i] = ((const float4*)W)[i];

    int row0 = blockIdx.x * ROWS;
    for (int i = t; i < ROWS * IN; i += 256) {
        int r = i / IN, c = i % IN;
        int gr = row0 + r;
        Xs[i] = (gr < NN) ? X[gr * IN + c] : 0.f;
    }
    __syncthreads();

    int cg = t % CG;
    int rb = (t / CG) * R;
    float4 acc[R];
#pragma unroll
    for (int j = 0; j < R; j++) acc[j] = make_float4(0.f, 0.f, 0.f, 0.f);

    const float4* Xs4 = (const float4*)Xs;
    constexpr int RS4 = IN / 4;
#pragma unroll 4
    for (int k4 = 0; k4 < IN / 4; k4++) {
        float4 w0 = Ws[(4 * k4 + 0) * CG + cg];
        float4 w1 = Ws[(4 * k4 + 1) * CG + cg];
        float4 w2 = Ws[(4 * k4 + 2) * CG + cg];
        float4 w3 = Ws[(4 * k4 + 3) * CG + cg];
#pragma unroll
        for (int j = 0; j < R; j++) {
            float4 xv = Xs4[(rb + j) * RS4 + k4];
            acc[j].x = fmaf(xv.x, w0.x, acc[j].x); acc[j].y = fmaf(xv.x, w0.y, acc[j].y);
            acc[j].z = fmaf(xv.x, w0.z, acc[j].z); acc[j].w = fmaf(xv.x, w0.w, acc[j].w);
            acc[j].x = fmaf(xv.y, w1.x, acc[j].x); acc[j].y = fmaf(xv.y, w1.y, acc[j].y);
            acc[j].z = fmaf(xv.y, w1.z, acc[j].z); acc[j].w = fmaf(xv.y, w1.w, acc[j].w);
            acc[j].x = fmaf(xv.z, w2.x, acc[j].x); acc[j].y = fmaf(xv.z, w2.y, acc[j].y);
            acc[j].z = fmaf(xv.z, w2.z, acc[j].z); acc[j].w = fmaf(xv.z, w2.w, acc[j].w);
            acc[j].x = fmaf(xv.w, w3.x, acc[j].x); acc[j].y = fmaf(xv.w, w3.y, acc[j].y);
            acc[j].z = fmaf(xv.w, w3.z, acc[j].z); acc[j].w = fmaf(xv.w, w3.w, acc[j].w);
        }
    }
#pragma unroll
    for (int j = 0; j < R; j++) {
        int grow = row0 + rb + j;
        if (grow < NN) {
            float dv = g_dinv[grow];
            float4 o = make_float4(acc[j].x * dv, acc[j].y * dv,
                                   acc[j].z * dv, acc[j].w * dv);
            ((float4*)Y)[grow * CG + cg] = o;
        }
    }
}

// ---------------- fused agg + next linear ----------------
// h = relu(dinv[i]*(Σ_nbr Y[src] + Y[i]) + b);  Ynext[i] = dinv[i]*(h @ W)
// 16 lanes/node, 16 nodes/block, grid = NN/16 exactly.
template <int OUTW>
__global__ void k_agg_lin(const float* __restrict__ bias, const float* __restrict__ W,
                          int ysel, int osel) {
    const float4* __restrict__ Y4 = (const float4*)bufsel(ysel, nullptr);
    float* Yo = bufsel(osel, nullptr);

    __shared__ float Ws[64 * OUTW];
    __shared__ float hs[16 * 64];

    int t = threadIdx.x;
    for (int i = t; i < 64 * OUTW / 4; i += 256)
        ((float4*)Ws)[i] = ((const float4*)W)[i];
    __syncthreads();

    int gid = t / 16, lane = t % 16;
    int node = blockIdx.x * 16 + gid;

    float4 acc = Y4[node * 16 + lane];          // self loop term
    int p = g_offs[node], end = g_offs[node + 1];
    const int* __restrict__ cs = g_csrc;
    for (; p + 4 <= end; p += 4) {
        int s0 = cs[p], s1 = cs[p + 1], s2 = cs[p + 2], s3 = cs[p + 3];
        float4 v0 = Y4[s0 * 16 + lane];
        float4 v1 = Y4[s1 * 16 + lane];
        float4 v2 = Y4[s2 * 16 + lane];
        float4 v3 = Y4[s3 * 16 + lane];
        acc.x += (v0.x + v1.x) + (v2.x + v3.x);
        acc.y += (v0.y + v1.y) + (v2.y + v3.y);
        acc.z += (v0.z + v1.z) + (v2.z + v3.z);
        acc.w += (v0.w + v1.w) + (v2.w + v3.w);
    }
    for (; p < end; ++p) {
        float4 v = Y4[cs[p] * 16 + lane];
        acc.x += v.x; acc.y += v.y; acc.z += v.z; acc.w += v.w;
    }

    float  dv = g_dinv[node];
    float4 bb = ((const float4*)bias)[lane];
    float4 h;
    h.x = fmaxf(fmaf(acc.x, dv, bb.x), 0.f);
    h.y = fmaxf(fmaf(acc.y, dv, bb.y), 0.f);
    h.z = fmaxf(fmaf(acc.z, dv, bb.z), 0.f);
    h.w = fmaxf(fmaf(acc.w, dv, bb.w), 0.f);
    ((float4*)hs)[gid * 16 + lane] = h;
    __syncwarp();

    const float4* h4s = (const float4*)(hs + gid * 64);
    if (OUTW == 64) {
        float4 o = make_float4(0.f, 0.f, 0.f, 0.f);
#pragma unroll 4
        for (int k4 = 0; k4 < 16; k4++) {
            float4 h4 = h4s[k4];
            float4 w0 = ((const float4*)Ws)[(4 * k4 + 0) * 16 + lane];
            float4 w1 = ((const float4*)Ws)[(4 * k4 + 1) * 16 + lane];
            float4 w2 = ((const float4*)Ws)[(4 * k4 + 2) * 16 + lane];
            float4 w3 = ((const float4*)Ws)[(4 * k4 + 3) * 16 + lane];
            o.x = fmaf(h4.x, w0.x, o.x); o.y = fmaf(h4.x, w0.y, o.y);
            o.z = fmaf(h4.x, w0.z, o.z); o.w = fmaf(h4.x, w0.w, o.w);
            o.x = fmaf(h4.y, w1.x, o.x); o.y = fmaf(h4.y, w1.y, o.y);
            o.z = fmaf(h4.y, w1.z, o.z); o.w = fmaf(h4.y, w1.w, o.w);
            o.x = fmaf(h4.z, w2.x, o.x); o.y = fmaf(h4.z, w2.y, o.y);
            o.z = fmaf(h4.z, w2.z, o.z); o.w = fmaf(h4.z, w2.w, o.w);
            o.x = fmaf(h4.w, w3.x, o.x); o.y = fmaf(h4.w, w3.y, o.y);
            o.z = fmaf(h4.w, w3.z, o.z); o.w = fmaf(h4.w, w3.w, o.w);
        }
        o.x *= dv; o.y *= dv; o.z *= dv; o.w *= dv;
        ((float4*)Yo)[node * 16 + lane] = o;
    } else {   // OUTW == 16: one output per lane
        float o = 0.f;
#pragma unroll 4
        for (int k4 = 0; k4 < 16; k4++) {
            float4 h4 = h4s[k4];
            o = fmaf(h4.x, Ws[(4 * k4 + 0) * 16 + lane], o);
            o = fmaf(h4.y, Ws[(4 * k4 + 1) * 16 + lane], o);
            o = fmaf(h4.z, Ws[(4 * k4 + 2) * 16 + lane], o);
            o = fmaf(h4.w, Ws[(4 * k4 + 3) * 16 + lane], o);
        }
        Yo[node * 16 + lane] = o * dv;
    }
}

// ---------------- final aggregation (16-wide, no relu) ----------------
__global__ void k_agg16(const float* __restrict__ bias, float* __restrict__ O) {
    const float4* __restrict__ Y4 = (const float4*)g_y3;
    int t    = threadIdx.x;
    int node = blockIdx.x * 64 + t / 4;
    if (node >= NN) return;
    int lane = t % 4;

    float4 acc = Y4[node * 4 + lane];
    int p = g_offs[node], end = g_offs[node + 1];
    const int* __restrict__ cs = g_csrc;
    for (; p + 4 <= end; p += 4) {
        int s0 = cs[p], s1 = cs[p + 1], s2 = cs[p + 2], s3 = cs[p + 3];
        float4 v0 = Y4[s0 * 4 + lane];
        float4 v1 = Y4[s1 * 4 + lane];
        float4 v2 = Y4[s2 * 4 + lane];
        float4 v3 = Y4[s3 * 4 + lane];
        acc.x += (v0.x + v1.x) + (v2.x + v3.x);
        acc.y += (v0.y + v1.y) + (v2.y + v3.y);
        acc.z += (v0.z + v1.z) + (v2.z + v3.z);
        acc.w += (v0.w + v1.w) + (v2.w + v3.w);
    }
    for (; p < end; ++p) {
        float4 v = Y4[cs[p] * 4 + lane];
        acc.x += v.x; acc.y += v.y; acc.z += v.z; acc.w += v.w;
    }
    float  dv = g_dinv[node];
    float4 bb = ((const float4*)bias)[lane];
    float4 o;
    o.x = fmaf(acc.x, dv, bb.x);
    o.y = fmaf(acc.y, dv, bb.y);
    o.z = fmaf(acc.z, dv, bb.z);
    o.w = fmaf(acc.w, dv, bb.w);
    ((float4*)O)[node * 4 + lane] = o;
}

// ---------------- launch ----------------
extern "C" void kernel_launch(void* const* d_in, const int* in_sizes, int n_in,
                              void* d_out, int out_size) {
    const float* x  = (const float*)d_in[0];
    const int*   ei = (const int*)d_in[1];
    const float* W1 = (const float*)d_in[2];
    const float* b1 = (const float*)d_in[3];
    const float* W2 = (const float*)d_in[4];
    const float* b2 = (const float*)d_in[5];
    const float* W3 = (const float*)d_in[6];
    const float* b3 = (const float*)d_in[7];
    float* out = (float*)d_out;

    // lin1: R=8 -> 128 rows/block. smem = 128*128*4 (Xs) + 128*16*16 (Ws) = 96KB
    constexpr int SM1 = (128 * 128 + 128 * 16 * 4) * 4;
    cudaFuncSetAttribute(k_linear<128, 64, 8>,
                         cudaFuncAttributeMaxDynamicSharedMemorySize, SM1);

    void* degp = nullptr;
    cudaGetSymbolAddress(&degp, g_deg);
    cudaMemsetAsync(degp, 0, NN * sizeof(int));

    // graph preprocessing (once per launch, reused by all 3 layers)
    k_detect <<<1,        256>>>(ei);
    k_hist   <<<NE / 256, 256>>>(ei);
    k_scan1  <<<NB_SCAN,  256>>>();
    k_scan23 <<<NB_SCAN,  256>>>();
    k_scatter<<<NE / 256, 256>>>(ei);

    // layer 1 transform: x @ W1 (scaled) -> g_y
    k_linear<128, 64, 8><<<(NN + 127) / 128, 256, SM1>>>(x, W1, 0);
    // agg1 + relu + lin2 fused: g_y -> g_h
    k_agg_lin<64><<<NN / 16, 256>>>(b1, W2, 0, 1);
    // agg2 + relu + lin3 fused: g_h -> g_y3
    k_agg_lin<16><<<NN / 16, 256>>>(b2, W3, 1, 2);
    // final aggregation: g_y3 -> out
    k_agg16<<<(NN + 63) / 64, 256>>>(b3, out);
}